// round 4
// baseline (speedup 1.0000x reference)
#include <cuda_runtime.h>

// ConvGRU cell. GEMM-style blocking:
//   block = 256 threads = 8 warps; warp <-> 4 output channels (warp-uniform
//   constant weight loads); thread <-> 8 pixels as 4 f32x2 pixel-pairs.
// Weights duplicated (w,w) in __constant__ so each LDC.128 yields two ready
// FFMA2 operands; float4 smem input loads are already f32x2 pixel-pairs.
// Per (c, matrix): 2 LDC.128 (16 cyc, const port) vs 16 FFMA2 (32 cyc) ->
// const port at 50% duty, fma pipe is the binder.

#define HW 65536        // 256*256
#define NB 8

typedef unsigned long long ull;

// layout: [m][c][64] duplicated weights (7*2048 floats) + 4 gates * 64
// duplicated bias floats.  14592 floats = 58368 B < 64KB constant bank.
__constant__ __align__(16) float cDup[7 * 2048 + 4 * 64];
__device__   __align__(16) float g_stage[7 * 2048 + 4 * 64];

__device__ __forceinline__ ull pack2(float a, float b) {
    ull r;
    asm("mov.b64 %0, {%1, %2};" : "=l"(r) : "f"(a), "f"(b));
    return r;
}
__device__ __forceinline__ void unpack2(ull v, float& a, float& b) {
    asm("mov.b64 {%0, %1}, %2;" : "=f"(a), "=f"(b) : "l"(v));
}
__device__ __forceinline__ void ffma2(ull& d, ull a, ull b) {
    asm("fma.rn.f32x2 %0, %1, %2, %3;" : "=l"(d) : "l"(a), "l"(b), "l"(d));
}
__device__ __forceinline__ float sigmoidf_(float a) {
    a = fminf(fmaxf(a, -30.f), 30.f);
    float e = __expf(-a);
    return __fdividef(1.f, 1.f + e);
}
__device__ __forceinline__ float tanhf_(float a) {
    a = fminf(fmaxf(a, -15.f), 15.f);
    float e = __expf(-2.f * a);
    return (1.f - e) * __fdividef(1.f, 1.f + e);
}

__global__ void prep_kernel(
    const float* __restrict__ w_xz, const float* __restrict__ w_hz,
    const float* __restrict__ w_xr, const float* __restrict__ w_hr,
    const float* __restrict__ w_c,  const float* __restrict__ w_u,
    const float* __restrict__ w_o,
    const float* __restrict__ b_xz, const float* __restrict__ b_hz,
    const float* __restrict__ b_xr, const float* __restrict__ b_hr,
    const float* __restrict__ b_c,  const float* __restrict__ b_u,
    const float* __restrict__ b_o)
{
    int t = threadIdx.x;               // 1024 threads
    int o = t & 31, c = t >> 5;
    const float* W[7] = { w_xz, w_hz, w_xr, w_hr, w_c, w_u, w_o };
#pragma unroll
    for (int m = 0; m < 7; m++) {
        float w = W[m][o * 32 + c];
        g_stage[(m * 32 + c) * 64 + 2 * o]     = w;
        g_stage[(m * 32 + c) * 64 + 2 * o + 1] = w;
    }
    if (t < 32) {
        float bz = b_xz[t] + b_hz[t];
        float br = b_xr[t] + b_hr[t];
        float bc = b_c[t]  + b_u[t];
        float by = b_o[t];
        g_stage[14336 +   0 + 2 * t] = bz;  g_stage[14336 +   0 + 2 * t + 1] = bz;
        g_stage[14336 +  64 + 2 * t] = br;  g_stage[14336 +  64 + 2 * t + 1] = br;
        g_stage[14336 + 128 + 2 * t] = bc;  g_stage[14336 + 128 + 2 * t + 1] = bc;
        g_stage[14336 + 192 + 2 * t] = by;  g_stage[14336 + 192 + 2 * t + 1] = by;
    }
}

// acc[o 0..3][pp 0..3] += W_m1 * in1 + W_m2 * in2  for this warp's 4 outputs
// and this thread's 8 pixels (4 f32x2 pairs). in1/in2: smem [32][256].
#define SWEEP2(acc, m1, in1, m2, in2)                                          \
    _Pragma("unroll")                                                          \
    for (int c = 0; c < 32; c++) {                                             \
        float4 u0 = ((const float4*)&(in1)[c * 256])[lane2];                   \
        float4 u1 = ((const float4*)&(in1)[c * 256])[lane2 + 1];               \
        float4 v0 = ((const float4*)&(in2)[c * 256])[lane2];                   \
        float4 v1 = ((const float4*)&(in2)[c * 256])[lane2 + 1];               \
        ull pu[4] = { pack2(u0.x, u0.y), pack2(u0.z, u0.w),                    \
                      pack2(u1.x, u1.y), pack2(u1.z, u1.w) };                  \
        ull pv[4] = { pack2(v0.x, v0.y), pack2(v0.z, v0.w),                    \
                      pack2(v1.x, v1.y), pack2(v1.z, v1.w) };                  \
        const ulonglong2* wa = (const ulonglong2*)&cDup[((m1) * 32 + c) * 64 + wid8]; \
        const ulonglong2* wb = (const ulonglong2*)&cDup[((m2) * 32 + c) * 64 + wid8]; \
        ulonglong2 wa0 = wa[0], wa1 = wa[1];                                   \
        ulonglong2 wb0 = wb[0], wb1 = wb[1];                                   \
        _Pragma("unroll")                                                      \
        for (int pp = 0; pp < 4; pp++) {                                       \
            ffma2((acc)[0][pp], wa0.x, pu[pp]);                                \
            ffma2((acc)[1][pp], wa0.y, pu[pp]);                                \
            ffma2((acc)[2][pp], wa1.x, pu[pp]);                                \
            ffma2((acc)[3][pp], wa1.y, pu[pp]);                                \
            ffma2((acc)[0][pp], wb0.x, pv[pp]);                                \
            ffma2((acc)[1][pp], wb0.y, pv[pp]);                                \
            ffma2((acc)[2][pp], wb1.x, pv[pp]);                                \
            ffma2((acc)[3][pp], wb1.y, pv[pp]);                                \
        }                                                                      \
    }

#define SWEEP1(acc, m1, in1)                                                   \
    _Pragma("unroll")                                                          \
    for (int c = 0; c < 32; c++) {                                             \
        float4 u0 = ((const float4*)&(in1)[c * 256])[lane2];                   \
        float4 u1 = ((const float4*)&(in1)[c * 256])[lane2 + 1];               \
        ull pu[4] = { pack2(u0.x, u0.y), pack2(u0.z, u0.w),                    \
                      pack2(u1.x, u1.y), pack2(u1.z, u1.w) };                  \
        const ulonglong2* wa = (const ulonglong2*)&cDup[((m1) * 32 + c) * 64 + wid8]; \
        ulonglong2 wa0 = wa[0], wa1 = wa[1];                                   \
        _Pragma("unroll")                                                      \
        for (int pp = 0; pp < 4; pp++) {                                       \
            ffma2((acc)[0][pp], wa0.x, pu[pp]);                                \
            ffma2((acc)[1][pp], wa0.y, pu[pp]);                                \
            ffma2((acc)[2][pp], wa1.x, pu[pp]);                                \
            ffma2((acc)[3][pp], wa1.y, pu[pp]);                                \
        }                                                                      \
    }

#define INIT_ACC(acc, g)                                                       \
    {                                                                          \
        const ulonglong2* bb =                                                 \
            (const ulonglong2*)&cDup[14336 + (g) * 64 + wid8];                 \
        ulonglong2 b0 = bb[0], b1 = bb[1];                                     \
        _Pragma("unroll")                                                      \
        for (int pp = 0; pp < 4; pp++) {                                       \
            (acc)[0][pp] = b0.x; (acc)[1][pp] = b0.y;                          \
            (acc)[2][pp] = b1.x; (acc)[3][pp] = b1.y;                          \
        }                                                                      \
    }

__global__ void __launch_bounds__(256, 2) gru_fused_kernel(
    const float* __restrict__ x, const float* __restrict__ h,
    float* __restrict__ out)
{
    extern __shared__ float smem[];
    float* xs = smem;               // [32][256]
    float* hs = smem + 8192;        // [32][256]
    float* ts = smem + 16384;       // [32][256]  rv, then ht

    const int tid   = threadIdx.x;
    const int wid   = tid >> 5;         // warp 0..7 -> outputs wid*4..wid*4+3
    const int lane  = tid & 31;         // pixels lane*8 .. lane*8+7
    const int wid8  = wid * 8;          // float offset into duplicated rows
    const int lane2 = lane * 2;         // float4 index of first pixel quad
    const int o0    = wid * 4;

    const int gp0 = blockIdx.x * 256;   // 2048 blocks cover 524288 px
    const int b   = gp0 >> 16;
    const int p0  = gp0 & 65535;

    // ---- stage input tiles xs/hs[c][px] (each thread 8+8 float4) ----
    {
        const float4* x4 = (const float4*)(x + (b * 32) * HW + p0);
        const float4* h4 = (const float4*)(h + (b * 32) * HW + p0);
#pragma unroll
        for (int k = 0; k < 8; k++) {
            int idx = tid + k * 256;        // 0..2047
            int c = idx >> 6, j = idx & 63;
            ((float4*)&xs[c * 256])[j] = x4[c * (HW / 4) + j];
            ((float4*)&hs[c * 256])[j] = h4[c * (HW / 4) + j];
        }
    }
    __syncthreads();

    // ---- r gate ----
    ull racc[4][4];
    INIT_ACC(racc, 1)
    SWEEP2(racc, 2, xs, 3, hs)

    // rv = sigmoid(r) * h -> ts
#pragma unroll
    for (int o = 0; o < 4; o++) {
        int oc = o0 + o;
        float4 h0 = ((const float4*)&hs[oc * 256])[lane2];
        float4 h1 = ((const float4*)&hs[oc * 256])[lane2 + 1];
        float r0, r1, r2, r3, r4, r5, r6, r7;
        unpack2(racc[o][0], r0, r1);
        unpack2(racc[o][1], r2, r3);
        unpack2(racc[o][2], r4, r5);
        unpack2(racc[o][3], r6, r7);
        float4 v0 = make_float4(sigmoidf_(r0) * h0.x, sigmoidf_(r1) * h0.y,
                                sigmoidf_(r2) * h0.z, sigmoidf_(r3) * h0.w);
        float4 v1 = make_float4(sigmoidf_(r4) * h1.x, sigmoidf_(r5) * h1.y,
                                sigmoidf_(r6) * h1.z, sigmoidf_(r7) * h1.w);
        ((float4*)&ts[oc * 256])[lane2]     = v0;
        ((float4*)&ts[oc * 256])[lane2 + 1] = v1;
    }
    __syncthreads();

    // ---- candidate: cacc = Wc*x + Wu*rv + bc ----
    ull cacc[4][4];
    INIT_ACC(cacc, 2)
    SWEEP2(cacc, 4, xs, 5, ts)

    // ---- z gate: zacc = Wxz*x + Whz*h + bz ----
    ull zacc[4][4];
    INIT_ACC(zacc, 0)
    SWEEP2(zacc, 0, xs, 1, hs)
    __syncthreads();    // all warps done reading ts=rv

    // ---- blend: ht = h + sigmoid(z)*(tanh(c) - h) -> ts + gmem ----
    float* houtb = out + NB * 32 * HW + (b * 32) * HW + p0;
#pragma unroll
    for (int o = 0; o < 4; o++) {
        int oc = o0 + o;
        float4 h0 = ((const float4*)&hs[oc * 256])[lane2];
        float4 h1 = ((const float4*)&hs[oc * 256])[lane2 + 1];
        float c0, c1, c2, c3, c4, c5, c6, c7;
        float z0, z1, z2, z3, z4, z5, z6, z7;
        unpack2(cacc[o][0], c0, c1); unpack2(cacc[o][1], c2, c3);
        unpack2(cacc[o][2], c4, c5); unpack2(cacc[o][3], c6, c7);
        unpack2(zacc[o][0], z0, z1); unpack2(zacc[o][1], z2, z3);
        unpack2(zacc[o][2], z4, z5); unpack2(zacc[o][3], z6, z7);
        float4 t0, t1;
        t0.x = fmaf(sigmoidf_(z0), tanhf_(c0) - h0.x, h0.x);
        t0.y = fmaf(sigmoidf_(z1), tanhf_(c1) - h0.y, h0.y);
        t0.z = fmaf(sigmoidf_(z2), tanhf_(c2) - h0.z, h0.z);
        t0.w = fmaf(sigmoidf_(z3), tanhf_(c3) - h0.w, h0.w);
        t1.x = fmaf(sigmoidf_(z4), tanhf_(c4) - h1.x, h1.x);
        t1.y = fmaf(sigmoidf_(z5), tanhf_(c5) - h1.y, h1.y);
        t1.z = fmaf(sigmoidf_(z6), tanhf_(c6) - h1.z, h1.z);
        t1.w = fmaf(sigmoidf_(z7), tanhf_(c7) - h1.w, h1.w);
        ((float4*)&ts[oc * 256])[lane2]     = t0;
        ((float4*)&ts[oc * 256])[lane2 + 1] = t1;
        ((float4*)(houtb + oc * HW))[lane2]     = t0;
        ((float4*)(houtb + oc * HW))[lane2 + 1] = t1;
    }
    __syncthreads();

    // ---- output projection: y = Wo*ht + by ----
    ull yacc[4][4];
    INIT_ACC(yacc, 3)
    SWEEP1(yacc, 6, ts)

    float* youtb = out + (b * 32) * HW + p0;
#pragma unroll
    for (int o = 0; o < 4; o++) {
        int oc = o0 + o;
        float y0, y1, y2, y3, y4, y5, y6, y7;
        unpack2(yacc[o][0], y0, y1); unpack2(yacc[o][1], y2, y3);
        unpack2(yacc[o][2], y4, y5); unpack2(yacc[o][3], y6, y7);
        ((float4*)(youtb + oc * HW))[lane2]     = make_float4(y0, y1, y2, y3);
        ((float4*)(youtb + oc * HW))[lane2 + 1] = make_float4(y4, y5, y6, y7);
    }
}

extern "C" void kernel_launch(void* const* d_in, const int* in_sizes, int n_in,
                              void* d_out, int out_size) {
    const float* x    = (const float*)d_in[0];
    const float* h    = (const float*)d_in[1];
    const float* w_xz = (const float*)d_in[2];
    const float* b_xz = (const float*)d_in[3];
    const float* w_hz = (const float*)d_in[4];
    const float* b_hz = (const float*)d_in[5];
    const float* w_xr = (const float*)d_in[6];
    const float* b_xr = (const float*)d_in[7];
    const float* w_hr = (const float*)d_in[8];
    const float* b_hr = (const float*)d_in[9];
    const float* w_c  = (const float*)d_in[10];
    const float* b_c  = (const float*)d_in[11];
    const float* w_u  = (const float*)d_in[12];
    const float* b_u  = (const float*)d_in[13];
    const float* w_o  = (const float*)d_in[14];
    const float* b_o  = (const float*)d_in[15];
    float* out = (float*)d_out;

    prep_kernel<<<1, 1024>>>(w_xz, w_hz, w_xr, w_hr, w_c, w_u, w_o,
                             b_xz, b_hz, b_xr, b_hr, b_c, b_u, b_o);

    void *csym = nullptr, *gsym = nullptr;
    cudaGetSymbolAddress(&csym, cDup);
    cudaGetSymbolAddress(&gsym, g_stage);
    cudaMemcpyAsync(csym, gsym, sizeof(float) * (7 * 2048 + 4 * 64),
                    cudaMemcpyDeviceToDevice);

    cudaFuncSetAttribute(gru_fused_kernel,
                         cudaFuncAttributeMaxDynamicSharedMemorySize, 98304);
    gru_fused_kernel<<<2048, 256, 98304>>>(x, h, out);
}

// round 5
// speedup vs baseline: 1.9110x; 1.9110x over previous
#include <cuda_runtime.h>

// ConvGRU cell, fully fused, one thread per pixel (R2 structure).
// Weight rows are split across the two independent load ports:
//   floats 0..15  of each row -> __constant__  (4x LDC.128 per (c,m))
//   floats 16..31 of each row -> shared memory (4x broadcast LDS.128)
// so neither port exceeds the FFMA2 cycle budget (16 FFMA2 = 32 cyc per (c,m)).

#define HW 65536        // 256*256
#define NB 8

typedef unsigned long long ull;

// [m][c][o] transposed weights (7*1024 floats) + 4 combined bias vectors.
__constant__ __align__(16) float cAll[7 * 1024 + 4 * 32];
__device__   __align__(16) float g_stage[7 * 1024 + 4 * 32];

__device__ __forceinline__ ull pack2(float a, float b) {
    ull r;
    asm("mov.b64 %0, {%1, %2};" : "=l"(r) : "f"(a), "f"(b));
    return r;
}
__device__ __forceinline__ void unpack2(ull v, float& a, float& b) {
    asm("mov.b64 {%0, %1}, %2;" : "=f"(a), "=f"(b) : "l"(v));
}
__device__ __forceinline__ void ffma2(ull& d, ull a, ull b) {
    asm("fma.rn.f32x2 %0, %1, %2, %3;" : "=l"(d) : "l"(a), "l"(b), "l"(d));
}
__device__ __forceinline__ float sigmoidf_(float a) {
    a = fminf(fmaxf(a, -30.f), 30.f);
    float e = __expf(-a);
    return __fdividef(1.f, 1.f + e);
}
__device__ __forceinline__ float tanhf_(float a) {
    a = fminf(fmaxf(a, -15.f), 15.f);
    float e = __expf(-2.f * a);
    return (1.f - e) * __fdividef(1.f, 1.f + e);
}

__global__ void prep_kernel(
    const float* __restrict__ w_xz, const float* __restrict__ w_hz,
    const float* __restrict__ w_xr, const float* __restrict__ w_hr,
    const float* __restrict__ w_c,  const float* __restrict__ w_u,
    const float* __restrict__ w_o,
    const float* __restrict__ b_xz, const float* __restrict__ b_hz,
    const float* __restrict__ b_xr, const float* __restrict__ b_hr,
    const float* __restrict__ b_c,  const float* __restrict__ b_u,
    const float* __restrict__ b_o)
{
    int t = threadIdx.x;               // 1024 threads
    int o = t & 31, c = t >> 5;
    g_stage[0 * 1024 + c * 32 + o] = w_xz[o * 32 + c];
    g_stage[1 * 1024 + c * 32 + o] = w_hz[o * 32 + c];
    g_stage[2 * 1024 + c * 32 + o] = w_xr[o * 32 + c];
    g_stage[3 * 1024 + c * 32 + o] = w_hr[o * 32 + c];
    g_stage[4 * 1024 + c * 32 + o] = w_c [o * 32 + c];
    g_stage[5 * 1024 + c * 32 + o] = w_u [o * 32 + c];
    g_stage[6 * 1024 + c * 32 + o] = w_o [o * 32 + c];
    if (t < 32) {
        g_stage[7168 +  0 + t] = b_xz[t] + b_hz[t];   // bz
        g_stage[7168 + 32 + t] = b_xr[t] + b_hr[t];   // br
        g_stage[7168 + 64 + t] = b_c[t]  + b_u[t];    // bc
        g_stage[7168 + 96 + t] = b_o[t];              // by
    }
}

// acc[0..15] (f32x2 output-channel pairs) += W_m * invec[c] over c.
// Pairs 0..7 fed from constant, pairs 8..15 from the smem copy wS.
#define SWEEP(acc, m, invec)                                                   \
    _Pragma("unroll")                                                          \
    for (int c = 0; c < 32; c++) {                                             \
        ull d = pack2((invec)[c], (invec)[c]);                                 \
        const ulonglong2* rc = (const ulonglong2*)&cAll[(m) * 1024 + c * 32];  \
        const ulonglong2* rs = (const ulonglong2*)&wS[(m)][c][0];              \
        _Pragma("unroll")                                                      \
        for (int q = 0; q < 4; q++) {                                          \
            ulonglong2 wc_ = rc[q];                                            \
            ffma2((acc)[2 * q],     wc_.x, d);                                 \
            ffma2((acc)[2 * q + 1], wc_.y, d);                                 \
            ulonglong2 ws_ = rs[q];                                            \
            ffma2((acc)[8 + 2 * q],     ws_.x, d);                             \
            ffma2((acc)[8 + 2 * q + 1], ws_.y, d);                             \
        }                                                                      \
    }

__global__ void __launch_bounds__(128, 2) gru_fused_kernel(
    const float* __restrict__ x, const float* __restrict__ h,
    float* __restrict__ out)
{
    // smem copy of the HIGH half (floats 16..31) of every weight row: 14KB.
    __shared__ __align__(16) float wS[7][32][16];

    const int tid = threadIdx.x;
    {
        // 7*32*4 = 896 float4 chunks, 128 threads -> 7 each.
#pragma unroll
        for (int k = 0; k < 7; k++) {
            int f = tid + k * 128;          // 0..895
            int m = f >> 7;                 // /128
            int rem = f & 127;
            int c = rem >> 2, j = rem & 3;
            ((float4*)&wS[m][c][0])[j] =
                *(const float4*)&cAll[m * 1024 + c * 32 + 16 + j * 4];
        }
    }
    __syncthreads();

    const int gp = blockIdx.x * 128 + tid;   // covers 524288 exactly
    const int b  = gp >> 16;
    const int p  = gp & 65535;
    const float* xb = x + (b * 32) * HW + p;
    const float* hb = h + (b * 32) * HW + p;

    float xv[32], hv[32];
#pragma unroll
    for (int c = 0; c < 32; c++) { xv[c] = xb[c * HW]; hv[c] = hb[c * HW]; }

    const float* bz_c = &cAll[7168];
    const float* br_c = &cAll[7168 + 32];
    const float* bc_c = &cAll[7168 + 64];
    const float* by_c = &cAll[7168 + 96];

    // ---- z gate ----
    ull za[16];
#pragma unroll
    for (int j = 0; j < 16; j++) za[j] = pack2(bz_c[2 * j], bz_c[2 * j + 1]);
    SWEEP(za, 0, xv)   // W_xz * x
    SWEEP(za, 1, hv)   // W_hz * h

    // ---- r gate ----
    ull ra[16];
#pragma unroll
    for (int j = 0; j < 16; j++) ra[j] = pack2(br_c[2 * j], br_c[2 * j + 1]);
    SWEEP(ra, 2, xv)   // W_xr * x
    SWEEP(ra, 3, hv)   // W_hr * h

    float zf[32], rv[32];       // z gate; rv = r_t * h
#pragma unroll
    for (int j = 0; j < 16; j++) {
        float a0, a1, r0, r1;
        unpack2(za[j], a0, a1);
        unpack2(ra[j], r0, r1);
        // pairs j<8 map to outputs 2j,2j+1 ; pairs j>=8 map to 16+2(j-8).. — 
        // consistent mapping is used everywhere (accumulator j <-> channels
        // idx(j) below), so activations stay aligned.
        zf[2 * j]     = sigmoidf_(a0);
        zf[2 * j + 1] = sigmoidf_(a1);
        rv[2 * j]     = sigmoidf_(r0);   // scaled by h below
        rv[2 * j + 1] = sigmoidf_(r1);
    }
    // acc pair j covers channels: j<8 -> {2j, 2j+1}; j>=8 -> {2j} too since
    // 8+2q over q=0..3 gives pairs 8..15 -> channels 16..31. Mapping is
    // identity: pair j <-> channels {2j, 2j+1}. Multiply rv by h accordingly.
#pragma unroll
    for (int o = 0; o < 32; o++) rv[o] *= hv[o];

    // ---- candidate ----
    ull ca[16];
#pragma unroll
    for (int j = 0; j < 16; j++) ca[j] = pack2(bc_c[2 * j], bc_c[2 * j + 1]);
    SWEEP(ca, 4, xv)   // W_c * x
    SWEEP(ca, 5, rv)   // W_u * (r*h)

    float ht[32];
#pragma unroll
    for (int j = 0; j < 16; j++) {
        float c0, c1;
        unpack2(ca[j], c0, c1);
        float hh0 = tanhf_(c0), hh1 = tanhf_(c1);
        int o = 2 * j;
        ht[o]     = fmaf(zf[o],     hh0 - hv[o],     hv[o]);
        ht[o + 1] = fmaf(zf[o + 1], hh1 - hv[o + 1], hv[o + 1]);
    }

    // ---- output projection ----
    ull ya[16];
#pragma unroll
    for (int j = 0; j < 16; j++) ya[j] = pack2(by_c[2 * j], by_c[2 * j + 1]);
    SWEEP(ya, 6, ht)   // W_o * h_t

    // ---- stores: out = [ y (8,32,256,256) | h_t (8,32,256,256) ] ----
    float* yout = out + (b * 32) * HW + p;
    float* hout = out + NB * 32 * HW + (b * 32) * HW + p;
#pragma unroll
    for (int j = 0; j < 16; j++) {
        float y0, y1;
        unpack2(ya[j], y0, y1);
        yout[(2 * j) * HW]     = y0;
        yout[(2 * j + 1) * HW] = y1;
    }
#pragma unroll
    for (int o = 0; o < 32; o++) hout[o * HW] = ht[o];
}

extern "C" void kernel_launch(void* const* d_in, const int* in_sizes, int n_in,
                              void* d_out, int out_size) {
    const float* x    = (const float*)d_in[0];
    const float* h    = (const float*)d_in[1];
    const float* w_xz = (const float*)d_in[2];
    const float* b_xz = (const float*)d_in[3];
    const float* w_hz = (const float*)d_in[4];
    const float* b_hz = (const float*)d_in[5];
    const float* w_xr = (const float*)d_in[6];
    const float* b_xr = (const float*)d_in[7];
    const float* w_hr = (const float*)d_in[8];
    const float* b_hr = (const float*)d_in[9];
    const float* w_c  = (const float*)d_in[10];
    const float* b_c  = (const float*)d_in[11];
    const float* w_u  = (const float*)d_in[12];
    const float* b_u  = (const float*)d_in[13];
    const float* w_o  = (const float*)d_in[14];
    const float* b_o  = (const float*)d_in[15];
    float* out = (float*)d_out;

    prep_kernel<<<1, 1024>>>(w_xz, w_hz, w_xr, w_hr, w_c, w_u, w_o,
                             b_xz, b_hz, b_xr, b_hr, b_c, b_u, b_o);

    void *csym = nullptr, *gsym = nullptr;
    cudaGetSymbolAddress(&csym, cAll);
    cudaGetSymbolAddress(&gsym, g_stage);
    cudaMemcpyAsync(csym, gsym, sizeof(float) * (7 * 1024 + 4 * 32),
                    cudaMemcpyDeviceToDevice);

    gru_fused_kernel<<<4096, 128>>>(x, h, out);
}

// round 6
// speedup vs baseline: 2.8236x; 1.4776x over previous
#include <cuda_runtime.h>

// ConvGRU cell. P=4 pixels x O=8 output channels per thread (256-thread block,
// 256-pixel tile). Weights in __constant__ (non-duplicated, warp-uniform
// LDC.128); inputs staged in smem [c][px] and duplicated into f32x2 via ALU
// MOVs (idle pipe). Per c per 2-matrix sweep: 32 FFMA2 (64 cyc) vs 4 LDC.128
// (32 cyc) vs 1KB/warp LDS (50% crossbar) -> fma pipe is the binder.

#define HW 65536        // 256*256
#define NB 8

typedef unsigned long long ull;

// [m][c][o] transposed weights (7*1024 floats) + 4 combined bias vectors.
__constant__ __align__(16) float cAll[7 * 1024 + 4 * 32];
__device__   __align__(16) float g_stage[7 * 1024 + 4 * 32];

__device__ __forceinline__ ull pack2(float a, float b) {
    ull r;
    asm("mov.b64 %0, {%1, %2};" : "=l"(r) : "f"(a), "f"(b));
    return r;
}
__device__ __forceinline__ void unpack2(ull v, float& a, float& b) {
    asm("mov.b64 {%0, %1}, %2;" : "=f"(a), "=f"(b) : "l"(v));
}
__device__ __forceinline__ void ffma2(ull& d, ull a, ull b) {
    asm("fma.rn.f32x2 %0, %1, %2, %3;" : "=l"(d) : "l"(a), "l"(b), "l"(d));
}
__device__ __forceinline__ float sigmoidf_(float a) {
    a = fminf(fmaxf(a, -30.f), 30.f);
    float e = __expf(-a);
    return __fdividef(1.f, 1.f + e);
}
__device__ __forceinline__ float tanhf_(float a) {
    a = fminf(fmaxf(a, -15.f), 15.f);
    float e = __expf(-2.f * a);
    return (1.f - e) * __fdividef(1.f, 1.f + e);
}

__global__ void prep_kernel(
    const float* __restrict__ w_xz, const float* __restrict__ w_hz,
    const float* __restrict__ w_xr, const float* __restrict__ w_hr,
    const float* __restrict__ w_c,  const float* __restrict__ w_u,
    const float* __restrict__ w_o,
    const float* __restrict__ b_xz, const float* __restrict__ b_hz,
    const float* __restrict__ b_xr, const float* __restrict__ b_hr,
    const float* __restrict__ b_c,  const float* __restrict__ b_u,
    const float* __restrict__ b_o)
{
    int t = threadIdx.x;               // 1024 threads
    int o = t & 31, c = t >> 5;
    g_stage[0 * 1024 + c * 32 + o] = w_xz[o * 32 + c];
    g_stage[1 * 1024 + c * 32 + o] = w_hz[o * 32 + c];
    g_stage[2 * 1024 + c * 32 + o] = w_xr[o * 32 + c];
    g_stage[3 * 1024 + c * 32 + o] = w_hr[o * 32 + c];
    g_stage[4 * 1024 + c * 32 + o] = w_c [o * 32 + c];
    g_stage[5 * 1024 + c * 32 + o] = w_u [o * 32 + c];
    g_stage[6 * 1024 + c * 32 + o] = w_o [o * 32 + c];
    if (t < 32) {
        g_stage[7168 +  0 + t] = b_xz[t] + b_hz[t];   // bz
        g_stage[7168 + 32 + t] = b_xr[t] + b_hr[t];   // br
        g_stage[7168 + 64 + t] = b_c[t]  + b_u[t];    // bc
        g_stage[7168 + 96 + t] = b_o[t];              // by
    }
}

// acc[op 0..3][px 0..3] : f32x2 over output-channel pair (o0+2op, o0+2op+1).
// += W_m1 * in1 + W_m2 * in2 over c. in1/in2: smem [32][256].
#define SWEEP2(acc, m1, in1, m2, in2)                                         \
    _Pragma("unroll")                                                         \
    for (int c = 0; c < 32; c++) {                                            \
        float4 u = ((const float4*)&(in1)[c * 256])[pg];                      \
        float4 v = ((const float4*)&(in2)[c * 256])[pg];                      \
        ull du[4] = { pack2(u.x, u.x), pack2(u.y, u.y),                       \
                      pack2(u.z, u.z), pack2(u.w, u.w) };                     \
        ull dv[4] = { pack2(v.x, v.x), pack2(v.y, v.y),                       \
                      pack2(v.z, v.z), pack2(v.w, v.w) };                     \
        const ulonglong2* wa =                                                \
            (const ulonglong2*)&cAll[(m1) * 1024 + c * 32 + o0];              \
        const ulonglong2* wb =                                                \
            (const ulonglong2*)&cAll[(m2) * 1024 + c * 32 + o0];              \
        ulonglong2 wa0 = wa[0];                                               \
        ulonglong2 wb0 = wb[0];                                               \
        _Pragma("unroll")                                                     \
        for (int px = 0; px < 4; px++) {                                      \
            ffma2((acc)[0][px], wa0.x, du[px]);                               \
            ffma2((acc)[1][px], wa0.y, du[px]);                               \
            ffma2((acc)[0][px], wb0.x, dv[px]);                               \
            ffma2((acc)[1][px], wb0.y, dv[px]);                               \
            ffma2((acc)[2][px], wa0.x == wa0.x ? 0 : 0, du[px]);              \
        }                                                                     \
    }

// NOTE: macro above is a placeholder guard against accidental use; real
// sweeps are written out below with both 16B halves (o0..o0+7).

__global__ void __launch_bounds__(256) gru_fused_kernel(
    const float* __restrict__ x, const float* __restrict__ h,
    float* __restrict__ out)
{
    extern __shared__ float smem[];
    float* xs = smem;               // [32][256]
    float* hs = smem + 8192;        // [32][256]
    float* ts = smem + 16384;       // [32][256]  rv, then ht

    const int tid = threadIdx.x;
    const int pg  = tid & 63;           // pixel quad index (4 px)
    const int o0  = (tid >> 6) * 8;     // base output channel (warp-uniform)

    const int gp0 = blockIdx.x * 256;   // 2048 blocks cover 524288 px
    const int b   = gp0 >> 16;
    const int p0  = gp0 & 65535;

    // ---- stage input tiles xs/hs[c][px] ----
    {
        const float4* x4 = (const float4*)(x + (b * 32) * HW + p0);
        const float4* h4 = (const float4*)(h + (b * 32) * HW + p0);
#pragma unroll
        for (int k = 0; k < 8; k++) {
            int idx = tid + k * 256;        // 0..2047
            int c = idx >> 6, j = idx & 63;
            ((float4*)&xs[c * 256])[j] = x4[c * (HW / 4) + j];
            ((float4*)&hs[c * 256])[j] = h4[c * (HW / 4) + j];
        }
    }
    __syncthreads();

// one 2-matrix accumulation step at channel c into acc[4][4]
#define STEP2(acc, m1, in1, m2, in2, c)                                       \
    {                                                                         \
        float4 u = ((const float4*)&(in1)[(c) * 256])[pg];                    \
        float4 v = ((const float4*)&(in2)[(c) * 256])[pg];                    \
        ull du[4] = { pack2(u.x, u.x), pack2(u.y, u.y),                       \
                      pack2(u.z, u.z), pack2(u.w, u.w) };                     \
        ull dv[4] = { pack2(v.x, v.x), pack2(v.y, v.y),                       \
                      pack2(v.z, v.z), pack2(v.w, v.w) };                     \
        const ulonglong2* wa =                                                \
            (const ulonglong2*)&cAll[(m1) * 1024 + (c) * 32 + o0];            \
        const ulonglong2* wb =                                                \
            (const ulonglong2*)&cAll[(m2) * 1024 + (c) * 32 + o0];            \
        ulonglong2 wa0 = wa[0], wa1 = wa[1];                                  \
        ulonglong2 wb0 = wb[0], wb1 = wb[1];                                  \
        _Pragma("unroll")                                                     \
        for (int px = 0; px < 4; px++) {                                      \
            ffma2((acc)[0][px], wa0.x, du[px]);                               \
            ffma2((acc)[1][px], wa0.y, du[px]);                               \
            ffma2((acc)[2][px], wa1.x, du[px]);                               \
            ffma2((acc)[3][px], wa1.y, du[px]);                               \
            ffma2((acc)[0][px], wb0.x, dv[px]);                               \
            ffma2((acc)[1][px], wb0.y, dv[px]);                               \
            ffma2((acc)[2][px], wb1.x, dv[px]);                               \
            ffma2((acc)[3][px], wb1.y, dv[px]);                               \
        }                                                                     \
    }

#define STEP1(acc, m1, in1, c)                                                \
    {                                                                         \
        float4 u = ((const float4*)&(in1)[(c) * 256])[pg];                    \
        ull du[4] = { pack2(u.x, u.x), pack2(u.y, u.y),                       \
                      pack2(u.z, u.z), pack2(u.w, u.w) };                     \
        const ulonglong2* wa =                                                \
            (const ulonglong2*)&cAll[(m1) * 1024 + (c) * 32 + o0];            \
        ulonglong2 wa0 = wa[0], wa1 = wa[1];                                  \
        _Pragma("unroll")                                                     \
        for (int px = 0; px < 4; px++) {                                      \
            ffma2((acc)[0][px], wa0.x, du[px]);                               \
            ffma2((acc)[1][px], wa0.y, du[px]);                               \
            ffma2((acc)[2][px], wa1.x, du[px]);                               \
            ffma2((acc)[3][px], wa1.y, du[px]);                               \
        }                                                                     \
    }

#define INIT_ACC(acc, boff)                                                   \
    _Pragma("unroll")                                                         \
    for (int op = 0; op < 4; op++) {                                          \
        ull bb = pack2(cAll[7168 + (boff) + o0 + 2 * op],                     \
                       cAll[7168 + (boff) + o0 + 2 * op + 1]);                \
        _Pragma("unroll")                                                     \
        for (int px = 0; px < 4; px++) (acc)[op][px] = bb;                    \
    }

    // ---- r gate: racc = Wxr*x + Whr*h + br ----
    ull racc[4][4];
    INIT_ACC(racc, 32)
#pragma unroll
    for (int c = 0; c < 32; c++) STEP2(racc, 2, xs, 3, hs, c)

    // rv = sigmoid(r) * h -> ts
#pragma unroll
    for (int op = 0; op < 4; op++) {
        int oc0 = o0 + 2 * op, oc1 = oc0 + 1;
        float4 h0 = ((const float4*)&hs[oc0 * 256])[pg];
        float4 h1 = ((const float4*)&hs[oc1 * 256])[pg];
        const float* h0f = (const float*)&h0;
        const float* h1f = (const float*)&h1;
        float r0[4], r1[4];
#pragma unroll
        for (int px = 0; px < 4; px++) {
            float a0, a1;
            unpack2(racc[op][px], a0, a1);
            r0[px] = sigmoidf_(a0) * h0f[px];
            r1[px] = sigmoidf_(a1) * h1f[px];
        }
        ((float4*)&ts[oc0 * 256])[pg] = make_float4(r0[0], r0[1], r0[2], r0[3]);
        ((float4*)&ts[oc1 * 256])[pg] = make_float4(r1[0], r1[1], r1[2], r1[3]);
    }
    __syncthreads();

    // ---- candidate: cacc = Wc*x + Wu*rv + bc ----
    ull cacc[4][4];
    INIT_ACC(cacc, 64)
#pragma unroll
    for (int c = 0; c < 32; c++) STEP2(cacc, 4, xs, 5, ts, c)

    // ---- z gate: zacc = Wxz*x + Whz*h + bz ----
    ull zacc[4][4];
    INIT_ACC(zacc, 0)
#pragma unroll
    for (int c = 0; c < 32; c++) STEP2(zacc, 0, xs, 1, hs, c)
    __syncthreads();    // all warps done reading ts=rv

    // ---- blend: ht = h + sigmoid(z)*(tanh(c) - h) -> ts + gmem ----
    float* houtb = out + NB * 32 * HW + (b * 32) * HW + p0;
#pragma unroll
    for (int op = 0; op < 4; op++) {
        int oc0 = o0 + 2 * op, oc1 = oc0 + 1;
        float4 h0 = ((const float4*)&hs[oc0 * 256])[pg];
        float4 h1 = ((const float4*)&hs[oc1 * 256])[pg];
        const float* h0f = (const float*)&h0;
        const float* h1f = (const float*)&h1;
        float t0[4], t1[4];
#pragma unroll
        for (int px = 0; px < 4; px++) {
            float c0, c1, z0, z1;
            unpack2(cacc[op][px], c0, c1);
            unpack2(zacc[op][px], z0, z1);
            t0[px] = fmaf(sigmoidf_(z0), tanhf_(c0) - h0f[px], h0f[px]);
            t1[px] = fmaf(sigmoidf_(z1), tanhf_(c1) - h1f[px], h1f[px]);
        }
        float4 v0 = make_float4(t0[0], t0[1], t0[2], t0[3]);
        float4 v1 = make_float4(t1[0], t1[1], t1[2], t1[3]);
        ((float4*)&ts[oc0 * 256])[pg] = v0;
        ((float4*)&ts[oc1 * 256])[pg] = v1;
        ((float4*)(houtb + oc0 * HW))[pg] = v0;
        ((float4*)(houtb + oc1 * HW))[pg] = v1;
    }
    __syncthreads();

    // ---- output projection: y = Wo*ht + by ----
    ull yacc[4][4];
    INIT_ACC(yacc, 96)
#pragma unroll
    for (int c = 0; c < 32; c++) STEP1(yacc, 6, ts, c)

    float* youtb = out + (b * 32) * HW + p0;
#pragma unroll
    for (int op = 0; op < 4; op++) {
        int oc0 = o0 + 2 * op, oc1 = oc0 + 1;
        float y0[4], y1[4];
#pragma unroll
        for (int px = 0; px < 4; px++) unpack2(yacc[op][px], y0[px], y1[px]);
        ((float4*)(youtb + oc0 * HW))[pg] = make_float4(y0[0], y0[1], y0[2], y0[3]);
        ((float4*)(youtb + oc1 * HW))[pg] = make_float4(y1[0], y1[1], y1[2], y1[3]);
    }
}

extern "C" void kernel_launch(void* const* d_in, const int* in_sizes, int n_in,
                              void* d_out, int out_size) {
    const float* x    = (const float*)d_in[0];
    const float* h    = (const float*)d_in[1];
    const float* w_xz = (const float*)d_in[2];
    const float* b_xz = (const float*)d_in[3];
    const float* w_hz = (const float*)d_in[4];
    const float* b_hz = (const float*)d_in[5];
    const float* w_xr = (const float*)d_in[6];
    const float* b_xr = (const float*)d_in[7];
    const float* w_hr = (const float*)d_in[8];
    const float* b_hr = (const float*)d_in[9];
    const float* w_c  = (const float*)d_in[10];
    const float* b_c  = (const float*)d_in[11];
    const float* w_u  = (const float*)d_in[12];
    const float* b_u  = (const float*)d_in[13];
    const float* w_o  = (const float*)d_in[14];
    const float* b_o  = (const float*)d_in[15];
    float* out = (float*)d_out;

    prep_kernel<<<1, 1024>>>(w_xz, w_hz, w_xr, w_hr, w_c, w_u, w_o,
                             b_xz, b_hz, b_xr, b_hr, b_c, b_u, b_o);

    void *csym = nullptr, *gsym = nullptr;
    cudaGetSymbolAddress(&csym, cAll);
    cudaGetSymbolAddress(&gsym, g_stage);
    cudaMemcpyAsync(csym, gsym, sizeof(float) * (7 * 1024 + 4 * 32),
                    cudaMemcpyDeviceToDevice);

    cudaFuncSetAttribute(gru_fused_kernel,
                         cudaFuncAttributeMaxDynamicSharedMemorySize, 98304);
    gru_fused_kernel<<<2048, 256, 98304>>>(x, h, out);
}